// round 4
// baseline (speedup 1.0000x reference)
#include <cuda_runtime.h>
#include <math.h>
#include <stdint.h>

#define BSZ    2048
#define LATENT 128
#define CCLS   8
#define HID    1024
#define DD     512
#define NMAXX  4096
#define NTG    128   // gemm kernels
#define NT     256   // aux kernels

__constant__ int c_counts[CCLS] = {1024, 1536, 2048, 2560, 3072, 3584, 3840, 4096};

__device__ __align__(16) float g_h[BSZ * HID];
__device__ __align__(16) float g_t[BSZ * HID];
__device__ __align__(16) float g_logits[(size_t)BSZ * NMAXX];
__device__ __align__(16) float g_colmean[CCLS * DD];
__device__ int g_order[BSZ];
__device__ int g_class_off[CCLS + 1];

__device__ __forceinline__ float gelu_exact(float x) {
    return 0.5f * x * (1.0f + erff(x * 0.70710678118654752f));
}
__device__ __forceinline__ uint32_t f2b(float f) { return __float_as_uint(f); }

__device__ __forceinline__ void mma8(float* d, const uint32_t* a, const uint32_t* b) {
    asm volatile(
        "mma.sync.aligned.m16n8k8.row.col.f32.tf32.tf32.f32 "
        "{%0,%1,%2,%3},{%4,%5,%6,%7},{%8,%9},{%0,%1,%2,%3};\n"
        : "+f"(d[0]), "+f"(d[1]), "+f"(d[2]), "+f"(d[3])
        : "r"(a[0]), "r"(a[1]), "r"(a[2]), "r"(a[3]), "r"(b[0]), "r"(b[1]));
}

__device__ __forceinline__ void cpa16(uint32_t dst, const float* src, bool pred) {
    int sz = pred ? 16 : 0;  // sz=0 -> zero-fill (deterministic)
    asm volatile("cp.async.cg.shared.global [%0], [%1], 16, %2;\n"
                 :: "r"(dst), "l"(src), "r"(sz));
}
#define CP_COMMIT asm volatile("cp.async.commit_group;\n")
#define CP_WAIT1  asm volatile("cp.async.wait_group 1;\n")

// Tile: block 64(M) x 128(N), K-step 16, 3 stages, 128 threads (4 warps 2x2),
// warp tile 32x64.
#define STAGES 3
#define ASTR 20
#define BSTR 136
#define AS_ELE (64 * ASTR)
#define BS_ELE (16 * BSTR)

#define GEMM_PROLOG \
    __shared__ float As[STAGES][AS_ELE]; \
    __shared__ float Bs[STAGES][BS_ELE]; \
    int tid = threadIdx.x; int lane = tid & 31; int wid = tid >> 5; \
    int wm = (wid & 1) * 32, wn = (wid >> 1) * 64; \
    int g = lane >> 2, tg = lane & 3; \
    float acc[2][8][4] = {}; \
    uint32_t aBase = (uint32_t)__cvta_generic_to_shared(&As[0][0]); \
    uint32_t bBase = (uint32_t)__cvta_generic_to_shared(&Bs[0][0]); \
    int am = tid >> 1, ak = (tid & 1) * 8; \
    int bkr = tid >> 5, bnr = (tid & 31) * 4;

#define PREF(it, buf) do { int _k0 = (it) * 16; \
    cpa16(aBase + (uint32_t)((buf)*AS_ELE + am*ASTR + ak)*4,          rA0 + _k0 + ak, pa0); \
    cpa16(aBase + (uint32_t)((buf)*AS_ELE + am*ASTR + ak + 4)*4,      rA0 + _k0 + ak + 4, pa0); \
    cpa16(bBase + (uint32_t)((buf)*BS_ELE + bkr*BSTR + bnr)*4,        Bsrc + (size_t)(_k0+bkr)*ldb + bnr, true); \
    cpa16(bBase + (uint32_t)((buf)*BS_ELE + (bkr+4)*BSTR + bnr)*4,    Bsrc + (size_t)(_k0+bkr+4)*ldb + bnr, true); \
    cpa16(bBase + (uint32_t)((buf)*BS_ELE + (bkr+8)*BSTR + bnr)*4,    Bsrc + (size_t)(_k0+bkr+8)*ldb + bnr, true); \
    cpa16(bBase + (uint32_t)((buf)*BS_ELE + (bkr+12)*BSTR + bnr)*4,   Bsrc + (size_t)(_k0+bkr+12)*ldb + bnr, true); \
} while (0)

#define COMPUTE(cur) do { \
    const float* AsP = As[cur]; const float* BsP = Bs[cur]; \
    _Pragma("unroll") for (int kk = 0; kk < 2; ++kk) { \
        uint32_t afr[2][4]; \
        _Pragma("unroll") for (int mi = 0; mi < 2; ++mi) { \
            const float* ap = AsP + (wm + mi*16 + g)*ASTR + kk*8 + tg; \
            afr[mi][0] = f2b(ap[0]);  afr[mi][1] = f2b(ap[8*ASTR]); \
            afr[mi][2] = f2b(ap[4]);  afr[mi][3] = f2b(ap[8*ASTR + 4]); } \
        uint32_t bfr[8][2]; \
        _Pragma("unroll") for (int ni = 0; ni < 8; ++ni) { \
            const float* bp = BsP + (kk*8 + tg)*BSTR + wn + ni*8 + g; \
            bfr[ni][0] = f2b(bp[0]);  bfr[ni][1] = f2b(bp[4*BSTR]); } \
        _Pragma("unroll") for (int mi = 0; mi < 2; ++mi) \
        _Pragma("unroll") for (int ni = 0; ni < 8; ++ni) \
            mma8(acc[mi][ni], afr[mi], bfr[ni]); \
    } } while (0)

#define MAINLOOP(KITERS) \
    PREF(0, 0); CP_COMMIT; \
    PREF(1, 1); CP_COMMIT; \
    for (int it = 0; it < (KITERS); ++it) { \
        int cur = it % STAGES; \
        CP_WAIT1; \
        __syncthreads(); \
        int nx = it + STAGES - 1; \
        if (nx < (KITERS)) { PREF(nx, nx % STAGES); } \
        CP_COMMIT; \
        COMPUTE(cur); \
    }

// ---------------------------------------------------------------------------
__global__ void group_kernel(const int* __restrict__ cls) {
    __shared__ int cnt[CCLS];
    __shared__ int off[CCLS + 1];
    int tid = threadIdx.x;
    if (tid < CCLS) cnt[tid] = 0;
    __syncthreads();
    for (int b = tid; b < BSZ; b += blockDim.x) atomicAdd(&cnt[cls[b]], 1);
    __syncthreads();
    if (tid == 0) {
        int s = 0;
        for (int c = 0; c < CCLS; c++) { off[c] = s; s += cnt[c]; }
        off[CCLS] = s;
        for (int c = 0; c <= CCLS; c++) g_class_off[c] = off[c];
    }
    __syncthreads();
    if (tid < CCLS) cnt[tid] = off[tid];
    __syncthreads();
    for (int b = tid; b < BSZ; b += blockDim.x) {
        int c = cls[b];
        int slot = atomicAdd(&cnt[c], 1);
        g_order[slot] = b;
    }
}

// ---------------------------------------------------------------------------
__global__ __launch_bounds__(NT) void k_colmean(const float* __restrict__ Xbuf) {
    int c = blockIdx.y;
    int dl = threadIdx.x & 63;
    int d = blockIdx.x * 64 + dl;
    int stripe = threadIdx.x >> 6;
    int cnt = c_counts[c];
    const float* X = Xbuf + (size_t)c * NMAXX * DD + d;
    float s = 0.f;
#pragma unroll 4
    for (int n = stripe; n < cnt; n += 4) s += X[(size_t)n * DD];
    __shared__ float red[NT];
    red[threadIdx.x] = s;
    __syncthreads();
    if (stripe == 0) {
        float tot = red[dl] + red[dl + 64] + red[dl + 128] + red[dl + 192];
        g_colmean[c * DD + d] = tot / (float)cnt;
    }
}

// ---------------------------------------------------------------------------
// Kernel 1: h = gelu(z @ W1[:128] + W1[128+cid] + b1)
// ---------------------------------------------------------------------------
__global__ __launch_bounds__(NTG, 4) void k_gemm_h(
    const float* __restrict__ z, const int* __restrict__ cls,
    const float* __restrict__ W1, const float* __restrict__ b1) {
    int m0 = blockIdx.y * 64, n0 = blockIdx.x * 128;
    GEMM_PROLOG
    const float* rA0 = z + (size_t)(m0 + am) * LATENT;
    bool pa0 = true;
    const float* Bsrc = W1 + n0; int ldb = HID;
    MAINLOOP(8)
#pragma unroll
    for (int mi = 0; mi < 2; ++mi)
#pragma unroll
    for (int r2 = 0; r2 < 2; ++r2) {
        int m = m0 + wm + mi * 16 + g + r2 * 8;
        int cid = cls[m];
        const float* wrow = W1 + (size_t)(LATENT + cid) * HID;
#pragma unroll
        for (int ni = 0; ni < 8; ++ni) {
            int n = n0 + wn + ni * 8 + tg * 2;
            float2 o;
            o.x = gelu_exact(acc[mi][ni][r2 * 2 + 0] + wrow[n] + b1[n]);
            o.y = gelu_exact(acc[mi][ni][r2 * 2 + 1] + wrow[n + 1] + b1[n + 1]);
            *(float2*)(g_h + (size_t)m * HID + n) = o;
        }
    }
}

// ---------------------------------------------------------------------------
// Kernel 2: t = gelu(h @ W2 + b2)
// ---------------------------------------------------------------------------
__global__ __launch_bounds__(NTG, 4) void k_gemm_t(
    const float* __restrict__ W2, const float* __restrict__ b2) {
    int m0 = blockIdx.y * 64, n0 = blockIdx.x * 128;
    GEMM_PROLOG
    const float* rA0 = g_h + (size_t)(m0 + am) * HID;
    bool pa0 = true;
    const float* Bsrc = W2 + n0; int ldb = HID;
    MAINLOOP(64)
#pragma unroll
    for (int mi = 0; mi < 2; ++mi)
#pragma unroll
    for (int r2 = 0; r2 < 2; ++r2) {
        int m = m0 + wm + mi * 16 + g + r2 * 8;
#pragma unroll
        for (int ni = 0; ni < 8; ++ni) {
            int n = n0 + wn + ni * 8 + tg * 2;
            float2 o;
            o.x = gelu_exact(acc[mi][ni][r2 * 2 + 0] + b2[n]);
            o.y = gelu_exact(acc[mi][ni][r2 * 2 + 1] + b2[n + 1]);
            *(float2*)(g_t + (size_t)m * HID + n) = o;
        }
    }
}

// ---------------------------------------------------------------------------
// Kernel 3: grouped logits
// ---------------------------------------------------------------------------
__global__ __launch_bounds__(NTG, 4) void k_logits(
    const float* __restrict__ Wa, const float* __restrict__ ba) {
    int c = blockIdx.z;
    int off = g_class_off[c];
    int Bc = g_class_off[c + 1] - off;
    int mt = blockIdx.y, nt = blockIdx.x;
    if (mt * 64 >= Bc) return;
    int cnt = c_counts[c];
    if (nt * 128 >= cnt) return;
    int m0 = mt * 64, n0 = nt * 128;
    GEMM_PROLOG
    bool pa0 = (m0 + am) < Bc;
    const float* rA0 = pa0 ? g_t + (size_t)g_order[off + m0 + am] * HID : g_t;
    const float* Bsrc = Wa + (size_t)c * HID * NMAXX + n0; int ldb = NMAXX;
    MAINLOOP(64)
    const float* baC = ba + (size_t)c * NMAXX;
#pragma unroll
    for (int mi = 0; mi < 2; ++mi)
#pragma unroll
    for (int r2 = 0; r2 < 2; ++r2) {
        int ml = m0 + wm + mi * 16 + g + r2 * 8;
        if (ml < Bc) {
            size_t row = (size_t)(off + ml) * NMAXX;
#pragma unroll
            for (int ni = 0; ni < 8; ++ni) {
                int n = n0 + wn + ni * 8 + tg * 2;
                float2 bb = *(const float2*)(baC + n);
                float2 o;
                o.x = acc[mi][ni][r2 * 2 + 0] + bb.x;
                o.y = acc[mi][ni][r2 * 2 + 1] + bb.y;
                *(float2*)(g_logits + row + n) = o;
            }
        }
    }
}

// ---------------------------------------------------------------------------
// Kernel 4: 2-pass online softmax; writes beta = alpha - 1/cnt in place
// ---------------------------------------------------------------------------
__global__ __launch_bounds__(NT) void k_softmax() {
    int r = blockIdx.x;
    int c = 0;
#pragma unroll
    for (int i = 1; i < CCLS; i++)
        if (r >= g_class_off[i]) c = i;
    int cnt = c_counts[c];
    float* row = g_logits + (size_t)r * NMAXX;
    int tid = threadIdx.x;
    __shared__ float redm[NT];
    __shared__ float reds[NT];

    // Pass 1: online max + sum
    float m = -1e30f, s = 0.f;
    for (int i = tid * 4; i < cnt; i += NT * 4) {
        float4 v = *(const float4*)(row + i);
        float lm = fmaxf(fmaxf(v.x, v.y), fmaxf(v.z, v.w));
        if (lm > m) { s *= __expf(m - lm); m = lm; }
        s += __expf(v.x - m) + __expf(v.y - m) + __expf(v.z - m) + __expf(v.w - m);
    }
    redm[tid] = m; reds[tid] = s;
    __syncthreads();
    for (int st = NT / 2; st > 0; st >>= 1) {
        if (tid < st) {
            float m1 = redm[tid], m2 = redm[tid + st];
            float M = fmaxf(m1, m2);
            reds[tid] = reds[tid] * __expf(m1 - M) + reds[tid + st] * __expf(m2 - M);
            redm[tid] = M;
        }
        __syncthreads();
    }
    float M = redm[0];
    float inv = 1.0f / reds[0];
    float invc = 1.0f / (float)cnt;

    // Pass 2: write beta
    for (int i = tid * 4; i < cnt; i += NT * 4) {
        float4 v = *(const float4*)(row + i);
        v.x = __expf(v.x - M) * inv - invc;
        v.y = __expf(v.y - M) * inv - invc;
        v.z = __expf(v.z - M) * inv - invc;
        v.w = __expf(v.w - M) * inv - invc;
        *(float4*)(row + i) = v;
    }
}

// ---------------------------------------------------------------------------
// Kernel 5: out[order[r]] = colmean[c] + beta @ Xbuf[c]
// ---------------------------------------------------------------------------
__global__ __launch_bounds__(NTG, 4) void k_out(
    const float* __restrict__ Xbuf, float* __restrict__ out) {
    int c = blockIdx.z;
    int off = g_class_off[c];
    int Bc = g_class_off[c + 1] - off;
    int mt = blockIdx.y, nt = blockIdx.x;
    if (mt * 64 >= Bc) return;
    int cnt = c_counts[c];
    int m0 = mt * 64, n0 = nt * 128;
    GEMM_PROLOG
    bool pa0 = (m0 + am) < Bc;
    const float* rA0 = pa0 ? g_logits + (size_t)(off + m0 + am) * NMAXX : g_logits;
    const float* Bsrc = Xbuf + (size_t)c * NMAXX * DD + n0; int ldb = DD;
    int kit = cnt / 16;
    MAINLOOP(kit)
    const float* cm = g_colmean + c * DD;
#pragma unroll
    for (int mi = 0; mi < 2; ++mi)
#pragma unroll
    for (int r2 = 0; r2 < 2; ++r2) {
        int ml = m0 + wm + mi * 16 + g + r2 * 8;
        if (ml < Bc) {
            int b = g_order[off + ml];
#pragma unroll
            for (int ni = 0; ni < 8; ++ni) {
                int n = n0 + wn + ni * 8 + tg * 2;
                float2 m2 = *(const float2*)(cm + n);
                float2 o;
                o.x = acc[mi][ni][r2 * 2 + 0] + m2.x;
                o.y = acc[mi][ni][r2 * 2 + 1] + m2.y;
                *(float2*)(out + (size_t)b * DD + n) = o;
            }
        }
    }
}

// ---------------------------------------------------------------------------
extern "C" void kernel_launch(void* const* d_in, const int* in_sizes, int n_in,
                              void* d_out, int out_size) {
    const float* z   = (const float*)d_in[0];
    const int*   cls = (const int*)d_in[1];
    const float* W1  = (const float*)d_in[2];
    const float* b1  = (const float*)d_in[3];
    const float* W2  = (const float*)d_in[4];
    const float* b2  = (const float*)d_in[5];
    const float* Wa  = (const float*)d_in[6];
    const float* ba  = (const float*)d_in[7];
    const float* Xb  = (const float*)d_in[8];
    float* out = (float*)d_out;

    group_kernel<<<1, NT>>>(cls);
    k_colmean<<<dim3(DD / 64, CCLS), NT>>>(Xb);
    k_gemm_h<<<dim3(HID / 128, BSZ / 64), NTG>>>(z, cls, W1, b1);
    k_gemm_t<<<dim3(HID / 128, BSZ / 64), NTG>>>(W2, b2);
    k_logits<<<dim3(NMAXX / 128, BSZ / 64, CCLS), NTG>>>(Wa, ba);
    k_softmax<<<BSZ, NT>>>();
    k_out<<<dim3(DD / 128, BSZ / 64, CCLS), NTG>>>(Xb, out);
}

// round 5
// speedup vs baseline: 1.1082x; 1.1082x over previous
#include <cuda_runtime.h>
#include <math.h>
#include <stdint.h>

#define BSZ    2048
#define LATENT 128
#define CCLS   8
#define HID    1024
#define DD     512
#define NMAXX  4096
#define NTG    128   // small gemm kernels
#define NT     256   // aux + large gemm kernels

__constant__ int c_counts[CCLS] = {1024, 1536, 2048, 2560, 3072, 3584, 3840, 4096};

__device__ __align__(16) float g_h[BSZ * HID];
__device__ __align__(16) float g_t[BSZ * HID];
__device__ __align__(16) float g_logits[(size_t)BSZ * NMAXX];
__device__ __align__(16) float g_colmean[CCLS * DD];
__device__ int g_order[BSZ];
__device__ int g_class_off[CCLS + 1];

__device__ __forceinline__ float gelu_exact(float x) {
    return 0.5f * x * (1.0f + erff(x * 0.70710678118654752f));
}
__device__ __forceinline__ uint32_t f2b(float f) { return __float_as_uint(f); }

__device__ __forceinline__ void mma8(float* d, const uint32_t* a, const uint32_t* b) {
    asm volatile(
        "mma.sync.aligned.m16n8k8.row.col.f32.tf32.tf32.f32 "
        "{%0,%1,%2,%3},{%4,%5,%6,%7},{%8,%9},{%0,%1,%2,%3};\n"
        : "+f"(d[0]), "+f"(d[1]), "+f"(d[2]), "+f"(d[3])
        : "r"(a[0]), "r"(a[1]), "r"(a[2]), "r"(a[3]), "r"(b[0]), "r"(b[1]));
}

__device__ __forceinline__ void cpa16(uint32_t dst, const float* src, bool pred) {
    int sz = pred ? 16 : 0;  // sz=0 -> zero-fill (deterministic)
    asm volatile("cp.async.cg.shared.global [%0], [%1], 16, %2;\n"
                 :: "r"(dst), "l"(src), "r"(sz));
}
#define CP_COMMIT asm volatile("cp.async.commit_group;\n")
#define CP_WAIT2  asm volatile("cp.async.wait_group 2;\n")

#define STAGES 4
#define ASTR 20
#define BSTR 136
#define BS_ELE (16 * BSTR)

// ========================= small config: 64x128, 128 thr =====================
#define AS_ELE_S (64 * ASTR)
#define GEMM_PROLOG_S \
    __shared__ float As[STAGES][AS_ELE_S]; \
    __shared__ float Bs[STAGES][BS_ELE]; \
    int tid = threadIdx.x; int lane = tid & 31; int wid = tid >> 5; \
    int wm = (wid & 1) * 32, wn = (wid >> 1) * 64; \
    int g = lane >> 2, tg = lane & 3; \
    float acc[2][8][4] = {}; \
    uint32_t aBase = (uint32_t)__cvta_generic_to_shared(&As[0][0]); \
    uint32_t bBase = (uint32_t)__cvta_generic_to_shared(&Bs[0][0]); \
    int am = tid >> 1, ak = (tid & 1) * 8; \
    int bkr = tid >> 5, bnr = (tid & 31) * 4;

#define PREF_S(it, buf) do { int _k0 = (it) * 16; \
    cpa16(aBase + (uint32_t)((buf)*AS_ELE_S + am*ASTR + ak)*4,        rA0 + _k0 + ak, pa0); \
    cpa16(aBase + (uint32_t)((buf)*AS_ELE_S + am*ASTR + ak + 4)*4,    rA0 + _k0 + ak + 4, pa0); \
    cpa16(bBase + (uint32_t)((buf)*BS_ELE + bkr*BSTR + bnr)*4,        Bsrc + (size_t)(_k0+bkr)*ldb + bnr, true); \
    cpa16(bBase + (uint32_t)((buf)*BS_ELE + (bkr+4)*BSTR + bnr)*4,    Bsrc + (size_t)(_k0+bkr+4)*ldb + bnr, true); \
    cpa16(bBase + (uint32_t)((buf)*BS_ELE + (bkr+8)*BSTR + bnr)*4,    Bsrc + (size_t)(_k0+bkr+8)*ldb + bnr, true); \
    cpa16(bBase + (uint32_t)((buf)*BS_ELE + (bkr+12)*BSTR + bnr)*4,   Bsrc + (size_t)(_k0+bkr+12)*ldb + bnr, true); \
} while (0)

#define COMPUTE_S(cur) do { \
    const float* AsP = As[cur]; const float* BsP = Bs[cur]; \
    _Pragma("unroll") for (int kk = 0; kk < 2; ++kk) { \
        uint32_t afr[2][4]; \
        _Pragma("unroll") for (int mi = 0; mi < 2; ++mi) { \
            const float* ap = AsP + (wm + mi*16 + g)*ASTR + kk*8 + tg; \
            afr[mi][0] = f2b(ap[0]);  afr[mi][1] = f2b(ap[8*ASTR]); \
            afr[mi][2] = f2b(ap[4]);  afr[mi][3] = f2b(ap[8*ASTR + 4]); } \
        uint32_t bfr[8][2]; \
        _Pragma("unroll") for (int ni = 0; ni < 8; ++ni) { \
            const float* bp = BsP + (kk*8 + tg)*BSTR + wn + ni*8 + g; \
            bfr[ni][0] = f2b(bp[0]);  bfr[ni][1] = f2b(bp[4*BSTR]); } \
        _Pragma("unroll") for (int mi = 0; mi < 2; ++mi) \
        _Pragma("unroll") for (int ni = 0; ni < 8; ++ni) \
            mma8(acc[mi][ni], afr[mi], bfr[ni]); \
    } } while (0)

#define MAINLOOP_S(KITERS) \
    PREF_S(0, 0); CP_COMMIT; \
    PREF_S(1, 1); CP_COMMIT; \
    PREF_S(2, 2); CP_COMMIT; \
    for (int it = 0; it < (KITERS); ++it) { \
        int cur = it & 3; \
        CP_WAIT2; \
        __syncthreads(); \
        int nx = it + STAGES - 1; \
        if (nx < (KITERS)) { PREF_S(nx, nx & 3); } \
        CP_COMMIT; \
        COMPUTE_S(cur); \
    }

// ========================= large config: 128x128, 256 thr ===================
#define AS_ELE_L (128 * ASTR)
#define GEMM_PROLOG_L \
    __shared__ float As[STAGES][AS_ELE_L]; \
    __shared__ float Bs[STAGES][BS_ELE]; \
    int tid = threadIdx.x; int lane = tid & 31; int wid = tid >> 5; \
    int wm = (wid & 3) * 32, wn = (wid >> 2) * 64; \
    int g = lane >> 2, tg = lane & 3; \
    float acc[2][8][4] = {}; \
    uint32_t aBase = (uint32_t)__cvta_generic_to_shared(&As[0][0]); \
    uint32_t bBase = (uint32_t)__cvta_generic_to_shared(&Bs[0][0]); \
    int am = tid >> 1, ak = (tid & 1) * 8; \
    int bkr = tid >> 5, bnr = (tid & 31) * 4;

#define PREF_L(it, buf) do { int _k0 = (it) * 16; \
    cpa16(aBase + (uint32_t)((buf)*AS_ELE_L + am*ASTR + ak)*4,        rA0 + _k0 + ak, pa0); \
    cpa16(aBase + (uint32_t)((buf)*AS_ELE_L + am*ASTR + ak + 4)*4,    rA0 + _k0 + ak + 4, pa0); \
    cpa16(bBase + (uint32_t)((buf)*BS_ELE + bkr*BSTR + bnr)*4,        Bsrc + (size_t)(_k0+bkr)*ldb + bnr, true); \
    cpa16(bBase + (uint32_t)((buf)*BS_ELE + (bkr+8)*BSTR + bnr)*4,    Bsrc + (size_t)(_k0+bkr+8)*ldb + bnr, true); \
} while (0)

#define COMPUTE_L(cur) COMPUTE_S(cur)

#define MAINLOOP_L(KITERS) \
    PREF_L(0, 0); CP_COMMIT; \
    PREF_L(1, 1); CP_COMMIT; \
    PREF_L(2, 2); CP_COMMIT; \
    for (int it = 0; it < (KITERS); ++it) { \
        int cur = it & 3; \
        CP_WAIT2; \
        __syncthreads(); \
        int nx = it + STAGES - 1; \
        if (nx < (KITERS)) { PREF_L(nx, nx & 3); } \
        CP_COMMIT; \
        COMPUTE_L(cur); \
    }

// ---------------------------------------------------------------------------
__global__ void group_kernel(const int* __restrict__ cls) {
    __shared__ int cnt[CCLS];
    __shared__ int off[CCLS + 1];
    int tid = threadIdx.x;
    if (tid < CCLS) cnt[tid] = 0;
    __syncthreads();
    for (int b = tid; b < BSZ; b += blockDim.x) atomicAdd(&cnt[cls[b]], 1);
    __syncthreads();
    if (tid == 0) {
        int s = 0;
        for (int c = 0; c < CCLS; c++) { off[c] = s; s += cnt[c]; }
        off[CCLS] = s;
        for (int c = 0; c <= CCLS; c++) g_class_off[c] = off[c];
    }
    __syncthreads();
    if (tid < CCLS) cnt[tid] = off[tid];
    __syncthreads();
    for (int b = tid; b < BSZ; b += blockDim.x) {
        int c = cls[b];
        int slot = atomicAdd(&cnt[c], 1);
        g_order[slot] = b;
    }
}

// ---------------------------------------------------------------------------
__global__ __launch_bounds__(NT) void k_colmean(const float* __restrict__ Xbuf) {
    int c = blockIdx.y;
    int dl = threadIdx.x & 63;
    int d = blockIdx.x * 64 + dl;
    int stripe = threadIdx.x >> 6;
    int cnt = c_counts[c];
    const float* X = Xbuf + (size_t)c * NMAXX * DD + d;
    float s = 0.f;
#pragma unroll 4
    for (int n = stripe; n < cnt; n += 4) s += X[(size_t)n * DD];
    __shared__ float red[NT];
    red[threadIdx.x] = s;
    __syncthreads();
    if (stripe == 0) {
        float tot = red[dl] + red[dl + 64] + red[dl + 128] + red[dl + 192];
        g_colmean[c * DD + d] = tot / (float)cnt;
    }
}

// ---------------------------------------------------------------------------
// Kernel 1: h = gelu(z @ W1[:128] + W1[128+cid] + b1)
// ---------------------------------------------------------------------------
__global__ __launch_bounds__(NTG, 4) void k_gemm_h(
    const float* __restrict__ z, const int* __restrict__ cls,
    const float* __restrict__ W1, const float* __restrict__ b1) {
    int m0 = blockIdx.y * 64, n0 = blockIdx.x * 128;
    GEMM_PROLOG_S
    const float* rA0 = z + (size_t)(m0 + am) * LATENT;
    bool pa0 = true;
    const float* Bsrc = W1 + n0; int ldb = HID;
    MAINLOOP_S(8)
#pragma unroll
    for (int mi = 0; mi < 2; ++mi)
#pragma unroll
    for (int r2 = 0; r2 < 2; ++r2) {
        int m = m0 + wm + mi * 16 + g + r2 * 8;
        int cid = cls[m];
        const float* wrow = W1 + (size_t)(LATENT + cid) * HID;
#pragma unroll
        for (int ni = 0; ni < 8; ++ni) {
            int n = n0 + wn + ni * 8 + tg * 2;
            float2 o;
            o.x = gelu_exact(acc[mi][ni][r2 * 2 + 0] + wrow[n] + b1[n]);
            o.y = gelu_exact(acc[mi][ni][r2 * 2 + 1] + wrow[n + 1] + b1[n + 1]);
            *(float2*)(g_h + (size_t)m * HID + n) = o;
        }
    }
}

// ---------------------------------------------------------------------------
// Kernel 2: t = gelu(h @ W2 + b2)
// ---------------------------------------------------------------------------
__global__ __launch_bounds__(NTG, 4) void k_gemm_t(
    const float* __restrict__ W2, const float* __restrict__ b2) {
    int m0 = blockIdx.y * 64, n0 = blockIdx.x * 128;
    GEMM_PROLOG_S
    const float* rA0 = g_h + (size_t)(m0 + am) * HID;
    bool pa0 = true;
    const float* Bsrc = W2 + n0; int ldb = HID;
    MAINLOOP_S(64)
#pragma unroll
    for (int mi = 0; mi < 2; ++mi)
#pragma unroll
    for (int r2 = 0; r2 < 2; ++r2) {
        int m = m0 + wm + mi * 16 + g + r2 * 8;
#pragma unroll
        for (int ni = 0; ni < 8; ++ni) {
            int n = n0 + wn + ni * 8 + tg * 2;
            float2 o;
            o.x = gelu_exact(acc[mi][ni][r2 * 2 + 0] + b2[n]);
            o.y = gelu_exact(acc[mi][ni][r2 * 2 + 1] + b2[n + 1]);
            *(float2*)(g_t + (size_t)m * HID + n) = o;
        }
    }
}

// ---------------------------------------------------------------------------
// Kernel 3: grouped logits, 128x128 tiles @ 256 threads
// ---------------------------------------------------------------------------
__global__ __launch_bounds__(NT, 2) void k_logits(
    const float* __restrict__ Wa, const float* __restrict__ ba) {
    int c = blockIdx.z;
    int off = g_class_off[c];
    int Bc = g_class_off[c + 1] - off;
    int mt = blockIdx.y, nt = blockIdx.x;
    if (mt * 128 >= Bc) return;
    int cnt = c_counts[c];
    if (nt * 128 >= cnt) return;
    int m0 = mt * 128, n0 = nt * 128;
    GEMM_PROLOG_L
    bool pa0 = (m0 + am) < Bc;
    const float* rA0 = pa0 ? g_t + (size_t)g_order[off + m0 + am] * HID : g_t;
    const float* Bsrc = Wa + (size_t)c * HID * NMAXX + n0; int ldb = NMAXX;
    MAINLOOP_L(64)
    const float* baC = ba + (size_t)c * NMAXX;
#pragma unroll
    for (int mi = 0; mi < 2; ++mi)
#pragma unroll
    for (int r2 = 0; r2 < 2; ++r2) {
        int ml = m0 + wm + mi * 16 + g + r2 * 8;
        if (ml < Bc) {
            size_t row = (size_t)(off + ml) * NMAXX;
#pragma unroll
            for (int ni = 0; ni < 8; ++ni) {
                int n = n0 + wn + ni * 8 + tg * 2;
                float2 bb = *(const float2*)(baC + n);
                float2 o;
                o.x = acc[mi][ni][r2 * 2 + 0] + bb.x;
                o.y = acc[mi][ni][r2 * 2 + 1] + bb.y;
                *(float2*)(g_logits + row + n) = o;
            }
        }
    }
}

// ---------------------------------------------------------------------------
// Kernel 4: smem-staged softmax; writes beta = alpha - 1/cnt in place.
// One global read + one global write per row.
// ---------------------------------------------------------------------------
__global__ __launch_bounds__(NT) void k_softmax() {
    __shared__ float buf[NMAXX];
    __shared__ float redm[NT];
    __shared__ float reds[NT];
    int r = blockIdx.x;
    int c = 0;
#pragma unroll
    for (int i = 1; i < CCLS; i++)
        if (r >= g_class_off[i]) c = i;
    int cnt = c_counts[c];
    float* row = g_logits + (size_t)r * NMAXX;
    int tid = threadIdx.x;

    // load row into smem + online max/sum
    float m = -1e30f, s = 0.f;
    for (int i = tid * 4; i < cnt; i += NT * 4) {
        float4 v = *(const float4*)(row + i);
        *(float4*)(buf + i) = v;
        float lm = fmaxf(fmaxf(v.x, v.y), fmaxf(v.z, v.w));
        if (lm > m) { s *= __expf(m - lm); m = lm; }
        s += __expf(v.x - m) + __expf(v.y - m) + __expf(v.z - m) + __expf(v.w - m);
    }
    redm[tid] = m; reds[tid] = s;
    __syncthreads();
    for (int st = NT / 2; st > 0; st >>= 1) {
        if (tid < st) {
            float m1 = redm[tid], m2 = redm[tid + st];
            float M = fmaxf(m1, m2);
            reds[tid] = reds[tid] * __expf(m1 - M) + reds[tid + st] * __expf(m2 - M);
            redm[tid] = M;
        }
        __syncthreads();
    }
    float M = redm[0];
    float inv = 1.0f / reds[0];
    float invc = 1.0f / (float)cnt;

    for (int i = tid * 4; i < cnt; i += NT * 4) {
        float4 v = *(const float4*)(buf + i);
        v.x = __expf(v.x - M) * inv - invc;
        v.y = __expf(v.y - M) * inv - invc;
        v.z = __expf(v.z - M) * inv - invc;
        v.w = __expf(v.w - M) * inv - invc;
        *(float4*)(row + i) = v;
    }
}

// ---------------------------------------------------------------------------
// Kernel 5: out[order[r]] = colmean[c] + beta @ Xbuf[c]
// ---------------------------------------------------------------------------
__global__ __launch_bounds__(NTG, 4) void k_out(
    const float* __restrict__ Xbuf, float* __restrict__ out) {
    int c = blockIdx.z;
    int off = g_class_off[c];
    int Bc = g_class_off[c + 1] - off;
    int mt = blockIdx.y, nt = blockIdx.x;
    if (mt * 64 >= Bc) return;
    int cnt = c_counts[c];
    int m0 = mt * 64, n0 = nt * 128;
    GEMM_PROLOG_S
    bool pa0 = (m0 + am) < Bc;
    const float* rA0 = pa0 ? g_logits + (size_t)(off + m0 + am) * NMAXX : g_logits;
    const float* Bsrc = Xbuf + (size_t)c * NMAXX * DD + n0; int ldb = DD;
    int kit = cnt / 16;
    MAINLOOP_S(kit)
    const float* cm = g_colmean + c * DD;
#pragma unroll
    for (int mi = 0; mi < 2; ++mi)
#pragma unroll
    for (int r2 = 0; r2 < 2; ++r2) {
        int ml = m0 + wm + mi * 16 + g + r2 * 8;
        if (ml < Bc) {
            int b = g_order[off + ml];
#pragma unroll
            for (int ni = 0; ni < 8; ++ni) {
                int n = n0 + wn + ni * 8 + tg * 2;
                float2 m2 = *(const float2*)(cm + n);
                float2 o;
                o.x = acc[mi][ni][r2 * 2 + 0] + m2.x;
                o.y = acc[mi][ni][r2 * 2 + 1] + m2.y;
                *(float2*)(out + (size_t)b * DD + n) = o;
            }
        }
    }
}

// ---------------------------------------------------------------------------
extern "C" void kernel_launch(void* const* d_in, const int* in_sizes, int n_in,
                              void* d_out, int out_size) {
    const float* z   = (const float*)d_in[0];
    const int*   cls = (const int*)d_in[1];
    const float* W1  = (const float*)d_in[2];
    const float* b1  = (const float*)d_in[3];
    const float* W2  = (const float*)d_in[4];
    const float* b2  = (const float*)d_in[5];
    const float* Wa  = (const float*)d_in[6];
    const float* ba  = (const float*)d_in[7];
    const float* Xb  = (const float*)d_in[8];
    float* out = (float*)d_out;

    group_kernel<<<1, NT>>>(cls);
    k_colmean<<<dim3(DD / 64, CCLS), NT>>>(Xb);
    k_gemm_h<<<dim3(HID / 128, BSZ / 64), NTG>>>(z, cls, W1, b1);
    k_gemm_t<<<dim3(HID / 128, BSZ / 64), NTG>>>(W2, b2);
    k_logits<<<dim3(NMAXX / 128, BSZ / 128, CCLS), NT>>>(Wa, ba);
    k_softmax<<<BSZ, NT>>>();
    k_out<<<dim3(DD / 128, BSZ / 64, CCLS), NTG>>>(Xb, out);
}